// round 1
// baseline (speedup 1.0000x reference)
#include <cuda_runtime.h>
#include <cstddef>

// EntmaxAttention (sparsemax attention), fp32, [B=2,H=16,S=2048,D=64], T=8.
//
// Per CTA: 16 query rows of one (b,h).
//   Phase 1: scores[16][2048] = (Q/8) @ K^T, tiled through smem (K transposed,
//            256-key blocks, 4x4 register micro-tile per thread).
//   Phase 2: warp-per-row sparsemax. Row's 2048 scores pulled into 64 regs/lane,
//            tau found by Michelot fixed-point iteration from tau0 = max-1
//            (monotone, bit-exact termination, warp-uniform early break).
//   Phase 3: sparse AV: ballot-scan register scores, gather V rows (L2) only
//            for support keys (~10 per row).

#define TQ        16
#define KB        256
#define SEQ       2048
#define DIM       64
#define NTHREADS  256
#define SMEM_FLOATS (TQ*SEQ + DIM*KB + DIM*TQ)   // 32768 + 16384 + 1024 = 50176
#define SMEM_BYTES  (SMEM_FLOATS * 4)            // 200704 B < 227 KB opt-in max

__global__ __launch_bounds__(NTHREADS, 1)
void entmax_attn_kernel(const float* __restrict__ Q, const float* __restrict__ K,
                        const float* __restrict__ V, float* __restrict__ O)
{
    extern __shared__ float smem[];
    float* ssc = smem;                 // [TQ][SEQ]  scores
    float* ksh = smem + TQ * SEQ;      // [DIM][KB]  K tile, transposed
    float* qsh = ksh + DIM * KB;       // [DIM][TQ]  Q tile, transposed, pre-scaled

    const int bh = blockIdx.y;
    const int q0 = blockIdx.x * TQ;
    const float* Qb = Q + ((size_t)bh * SEQ + q0) * DIM;
    const float* Kb = K + (size_t)bh * SEQ * DIM;
    const float* Vb = V + (size_t)bh * SEQ * DIM;
    float*       Ob = O + ((size_t)bh * SEQ + q0) * DIM;

    const int tid = threadIdx.x;
    const float invT = 0.125f;

    // Load Q tile transposed, folding in the 1/temperature scale.
    for (int i = tid; i < TQ * DIM; i += NTHREADS) {
        int r = i >> 6;          // row 0..15
        int d = i & 63;          // dim 0..63
        qsh[d * TQ + r] = Qb[r * DIM + d] * invT;
    }

    // ---------------- Phase 1: score GEMM ----------------
    const int rg = tid >> 6;   // 0..3  -> rows 4*rg .. 4*rg+3
    const int kg = tid & 63;   // 0..63 -> keys 4*kg .. 4*kg+3 within block

    for (int kb0 = 0; kb0 < SEQ; kb0 += KB) {
        __syncthreads();   // qsh ready (iter 0) / ksh no longer in use (iters>0)

        // Each thread loads one K row (256 rows / 256 threads), stores transposed.
        {
            const float4* krow =
                reinterpret_cast<const float4*>(Kb + (size_t)(kb0 + tid) * DIM);
            #pragma unroll
            for (int d4 = 0; d4 < DIM / 4; ++d4) {
                float4 kv = krow[d4];
                ksh[(d4 * 4 + 0) * KB + tid] = kv.x;
                ksh[(d4 * 4 + 1) * KB + tid] = kv.y;
                ksh[(d4 * 4 + 2) * KB + tid] = kv.z;
                ksh[(d4 * 4 + 3) * KB + tid] = kv.w;
            }
        }
        __syncthreads();

        float4 a0 = {0.f,0.f,0.f,0.f}, a1 = {0.f,0.f,0.f,0.f};
        float4 a2 = {0.f,0.f,0.f,0.f}, a3 = {0.f,0.f,0.f,0.f};

        #pragma unroll 16
        for (int d = 0; d < DIM; ++d) {
            float4 qv = *reinterpret_cast<const float4*>(qsh + d * TQ + 4 * rg); // broadcast
            float4 kv = *reinterpret_cast<const float4*>(ksh + d * KB + 4 * kg); // conflict-free
            a0.x += qv.x * kv.x; a0.y += qv.x * kv.y; a0.z += qv.x * kv.z; a0.w += qv.x * kv.w;
            a1.x += qv.y * kv.x; a1.y += qv.y * kv.y; a1.z += qv.y * kv.z; a1.w += qv.y * kv.w;
            a2.x += qv.z * kv.x; a2.y += qv.z * kv.y; a2.z += qv.z * kv.z; a2.w += qv.z * kv.w;
            a3.x += qv.w * kv.x; a3.y += qv.w * kv.y; a3.z += qv.w * kv.z; a3.w += qv.w * kv.w;
        }

        float* sb = ssc + (size_t)(4 * rg) * SEQ + kb0 + 4 * kg;
        *reinterpret_cast<float4*>(sb + 0 * SEQ) = a0;
        *reinterpret_cast<float4*>(sb + 1 * SEQ) = a1;
        *reinterpret_cast<float4*>(sb + 2 * SEQ) = a2;
        *reinterpret_cast<float4*>(sb + 3 * SEQ) = a3;
    }
    __syncthreads();

    // ---------------- Phase 2+3: sparsemax + sparse AV ----------------
    const int warp = tid >> 5;
    const int lane = tid & 31;

    for (int rr = 0; rr < 2; ++rr) {
        const int r = warp * 2 + rr;

        // Pull this row's 2048 scores into registers: lane holds keys 32*j + lane.
        float sreg[64];
        const float* srow = ssc + (size_t)r * SEQ;
        #pragma unroll
        for (int j = 0; j < 64; ++j) sreg[j] = srow[j * 32 + lane];

        // Row max.
        float m = sreg[0];
        #pragma unroll
        for (int j = 1; j < 64; ++j) m = fmaxf(m, sreg[j]);
        #pragma unroll
        for (int off = 16; off; off >>= 1)
            m = fmaxf(m, __shfl_xor_sync(0xffffffffu, m, off));

        // Michelot fixed-point iteration from tau0 = max - 1 (<= tau*).
        // Monotone increasing; terminates bit-exactly when support stabilizes.
        float tau = m - 1.0f;
        for (int it = 0; it < 32; ++it) {
            float ssum = 0.0f, cnt = 0.0f;
            #pragma unroll
            for (int j = 0; j < 64; ++j) {
                if (sreg[j] > tau) { ssum += sreg[j]; cnt += 1.0f; }
            }
            #pragma unroll
            for (int off = 16; off; off >>= 1) {
                ssum += __shfl_xor_sync(0xffffffffu, ssum, off);
                cnt  += __shfl_xor_sync(0xffffffffu, cnt,  off);
            }
            float nt = (ssum - 1.0f) / cnt;   // cnt >= 1 always (row max in support)
            if (nt == tau) break;             // warp-uniform
            tau = nt;
        }

        // Sparse AV: only support keys (p > 0) touch V. Lane covers out dims
        // {lane, lane+32}.
        float o0 = 0.0f, o1 = 0.0f;
        #pragma unroll
        for (int j = 0; j < 64; ++j) {
            float p = sreg[j] - tau;
            unsigned mset = __ballot_sync(0xffffffffu, p > 0.0f);
            while (mset) {
                int b = __ffs(mset) - 1;
                mset &= mset - 1;
                float pb = __shfl_sync(0xffffffffu, p, b);
                const float* vrow = Vb + (size_t)(j * 32 + b) * DIM;
                o0 += pb * vrow[lane];
                o1 += pb * vrow[lane + 32];
            }
        }
        Ob[r * DIM + lane]      = o0;
        Ob[r * DIM + lane + 32] = o1;
    }
}

extern "C" void kernel_launch(void* const* d_in, const int* in_sizes, int n_in,
                              void* d_out, int out_size)
{
    const float* q = (const float*)d_in[0];
    const float* k = (const float*)d_in[1];
    const float* v = (const float*)d_in[2];
    float*       o = (float*)d_out;

    const int BH = in_sizes[0] / (SEQ * DIM);   // 32 for [2,16,2048,64]

    cudaFuncSetAttribute(entmax_attn_kernel,
                         cudaFuncAttributeMaxDynamicSharedMemorySize, SMEM_BYTES);

    dim3 grid(SEQ / TQ, BH);
    entmax_attn_kernel<<<grid, NTHREADS, SMEM_BYTES>>>(q, k, v, o);
}

// round 3
// speedup vs baseline: 1.1740x; 1.1740x over previous
#include <cuda_runtime.h>
#include <cstddef>

// EntmaxAttention (sparsemax attention), fp32, [B=2,H=16,S=2048,D=64], T=8.
//
// R2 = R1 resubmission (broker timeout, never measured):
// 512 threads/CTA (16 warps), f32x2 packed FFMA (rows paired, free pack via
// transposed qsh), register-prefetched K tiles, bank-conflict-free transposed
// K stores. Phase 2/3: warp-per-row Michelot sparsemax + sparse AV gather.

#define TQ        16
#define KB        256
#define SEQ       2048
#define DIM       64
#define NTHREADS  512
#define SMEM_FLOATS (TQ*SEQ + DIM*KB + DIM*TQ)   // 32768 + 16384 + 1024 = 50176
#define SMEM_BYTES  (SMEM_FLOATS * 4)            // 200704 B

__device__ __forceinline__ void fma2(unsigned long long &d,
                                     unsigned long long a,
                                     unsigned long long b)
{
    asm("fma.rn.f32x2 %0, %1, %2, %0;" : "+l"(d) : "l"(a), "l"(b));
}

__device__ __forceinline__ unsigned long long dup2(float x)
{
    unsigned long long r;
    asm("mov.b64 %0, {%1, %1};" : "=l"(r) : "f"(x));
    return r;
}

__global__ __launch_bounds__(NTHREADS, 1)
void entmax_attn_kernel(const float* __restrict__ Q, const float* __restrict__ K,
                        const float* __restrict__ V, float* __restrict__ O)
{
    extern __shared__ float smem[];
    float* ssc = smem;                 // [TQ][SEQ]  scores
    float* ksh = smem + TQ * SEQ;      // [DIM][KB]  K tile, transposed
    float* qsh = ksh + DIM * KB;       // [DIM][TQ]  Q tile, transposed, pre-scaled

    const int bh = blockIdx.y;
    const int q0 = blockIdx.x * TQ;
    const float* Qb = Q + ((size_t)bh * SEQ + q0) * DIM;
    const float* Kb = K + (size_t)bh * SEQ * DIM;
    const float* Vb = V + (size_t)bh * SEQ * DIM;
    float*       Ob = O + ((size_t)bh * SEQ + q0) * DIM;

    const int tid = threadIdx.x;

    // Q tile, transposed, pre-scaled by 1/T. Row pairs (2r, 2r+1) become
    // contiguous 8B units -> free u64 operand pairs for f32x2.
    for (int i = tid; i < TQ * DIM; i += NTHREADS) {
        int r = i >> 6;
        int d = i & 63;
        qsh[d * TQ + r] = Qb[r * DIM + d] * 0.125f;
    }

    // K loader mapping: 2 threads per K row, split by d-half. Warp lanes cover
    // 32 consecutive rows -> transposed STS.32 hits 32 distinct banks.
    const int krow  = tid & 255;
    const int khalf = tid >> 8;        // 0: d 0..31, 1: d 32..63

    // Prefetch K block 0 into registers.
    float4 pf[8];
    {
        const float4* src =
            reinterpret_cast<const float4*>(Kb + (size_t)krow * DIM + khalf * 32);
        #pragma unroll
        for (int i = 0; i < 8; ++i) pf[i] = src[i];
    }

    // ---------------- Phase 1: score GEMM ----------------
    const int rg = tid >> 7;    // 0..3  -> rows 4*rg .. 4*rg+3
    const int kg = tid & 127;   // 0..127 -> keys 2*kg, 2*kg+1

    for (int kb0 = 0; kb0 < SEQ; kb0 += KB) {
        __syncthreads();   // prev compute done with ksh; qsh writes ordered (iter 0)

        // Store prefetched K transposed (conflict-free).
        #pragma unroll
        for (int i = 0; i < 8; ++i) {
            int dbase = khalf * 32 + i * 4;
            ksh[(dbase + 0) * KB + krow] = pf[i].x;
            ksh[(dbase + 1) * KB + krow] = pf[i].y;
            ksh[(dbase + 2) * KB + krow] = pf[i].z;
            ksh[(dbase + 3) * KB + krow] = pf[i].w;
        }
        __syncthreads();

        // Prefetch next K block; LDG latency hides under the d-loop below.
        if (kb0 + KB < SEQ) {
            const float4* src = reinterpret_cast<const float4*>(
                Kb + (size_t)(kb0 + KB + krow) * DIM + khalf * 32);
            #pragma unroll
            for (int i = 0; i < 8; ++i) pf[i] = src[i];
        }

        // acc[p][k]: p = row pair (rows 4rg+2p, 4rg+2p+1), k = key (2kg+k).
        unsigned long long a00 = 0ull, a01 = 0ull, a10 = 0ull, a11 = 0ull;

        #pragma unroll 16
        for (int d = 0; d < DIM; ++d) {
            // (q[4rg],q[4rg+1]) and (q[4rg+2],q[4rg+3]) as packed u64 (broadcast)
            ulonglong2 qq =
                *reinterpret_cast<const ulonglong2*>(qsh + d * TQ + 4 * rg);
            float2 kv = *reinterpret_cast<const float2*>(ksh + d * KB + 2 * kg);
            unsigned long long k0 = dup2(kv.x);
            unsigned long long k1 = dup2(kv.y);
            fma2(a00, qq.x, k0); fma2(a01, qq.x, k1);
            fma2(a10, qq.y, k0); fma2(a11, qq.y, k1);
        }

        // Unpack and store scores (row-major float2 per row).
        float2 f00 = *reinterpret_cast<float2*>(&a00);
        float2 f01 = *reinterpret_cast<float2*>(&a01);
        float2 f10 = *reinterpret_cast<float2*>(&a10);
        float2 f11 = *reinterpret_cast<float2*>(&a11);
        float* sb = ssc + (size_t)(4 * rg) * SEQ + kb0 + 2 * kg;
        *reinterpret_cast<float2*>(sb + 0 * SEQ) = make_float2(f00.x, f01.x);
        *reinterpret_cast<float2*>(sb + 1 * SEQ) = make_float2(f00.y, f01.y);
        *reinterpret_cast<float2*>(sb + 2 * SEQ) = make_float2(f10.x, f11.x);
        *reinterpret_cast<float2*>(sb + 3 * SEQ) = make_float2(f10.y, f11.y);
    }
    __syncthreads();

    // ---------------- Phase 2+3: sparsemax + sparse AV ----------------
    const int warp = tid >> 5;   // 0..15 -> row
    const int lane = tid & 31;
    const int r = warp;

    // Pull row's 2048 scores into registers: lane holds keys 32*j + lane.
    float sreg[64];
    const float* srow = ssc + (size_t)r * SEQ;
    #pragma unroll
    for (int j = 0; j < 64; ++j) sreg[j] = srow[j * 32 + lane];

    // Row max.
    float m = sreg[0];
    #pragma unroll
    for (int j = 1; j < 64; ++j) m = fmaxf(m, sreg[j]);
    #pragma unroll
    for (int off = 16; off; off >>= 1)
        m = fmaxf(m, __shfl_xor_sync(0xffffffffu, m, off));

    // Michelot fixed-point iteration from tau0 = max - 1 (<= tau*).
    // Monotone increasing; terminates bit-exactly when support stabilizes.
    float tau = m - 1.0f;
    for (int it = 0; it < 32; ++it) {
        float ssum = 0.0f, cnt = 0.0f;
        #pragma unroll
        for (int j = 0; j < 64; ++j) {
            if (sreg[j] > tau) { ssum += sreg[j]; cnt += 1.0f; }
        }
        #pragma unroll
        for (int off = 16; off; off >>= 1) {
            ssum += __shfl_xor_sync(0xffffffffu, ssum, off);
            cnt  += __shfl_xor_sync(0xffffffffu, cnt,  off);
        }
        float nt = (ssum - 1.0f) / cnt;   // cnt >= 1 (row max always in support)
        if (nt == tau) break;             // warp-uniform
        tau = nt;
    }

    // Sparse AV: only support keys (p > 0) touch V. Lane covers out dims
    // {lane, lane+32}.
    float o0 = 0.0f, o1 = 0.0f;
    #pragma unroll
    for (int j = 0; j < 64; ++j) {
        float p = sreg[j] - tau;
        unsigned mset = __ballot_sync(0xffffffffu, p > 0.0f);
        while (mset) {
            int b = __ffs(mset) - 1;
            mset &= mset - 1;
            float pb = __shfl_sync(0xffffffffu, p, b);
            const float* vrow = Vb + (size_t)(j * 32 + b) * DIM;
            o0 += pb * vrow[lane];
            o1 += pb * vrow[lane + 32];
        }
    }
    Ob[r * DIM + lane]      = o0;
    Ob[r * DIM + lane + 32] = o1;
}

extern "C" void kernel_launch(void* const* d_in, const int* in_sizes, int n_in,
                              void* d_out, int out_size)
{
    const float* q = (const float*)d_in[0];
    const float* k = (const float*)d_in[1];
    const float* v = (const float*)d_in[2];
    float*       o = (float*)d_out;

    const int BH = in_sizes[0] / (SEQ * DIM);   // 32 for [2,16,2048,64]

    cudaFuncSetAttribute(entmax_attn_kernel,
                         cudaFuncAttributeMaxDynamicSharedMemorySize, SMEM_BYTES);

    dim3 grid(SEQ / TQ, BH);
    entmax_attn_kernel<<<grid, NTHREADS, SMEM_BYTES>>>(q, k, v, o);
}

// round 10
// speedup vs baseline: 1.8238x; 1.5535x over previous
#include <cuda_runtime.h>
#include <cuda_bf16.h>
#include <cstdint>
#include <cstddef>

// EntmaxAttention, fp32 [B=2,H=16,S=2048,D=64], T=8.
// mma.sync.m16n8k16 bf16 (HMMA; tcgen05 rejected by harness toolchain: PTX
// targets sm_103 without the 'a' feature).
//
// Per CTA: 16 q rows. Q,K split 2-term bf16 (Dekker); scores = 3 MMA products
// (AhBh + AlBh + AhBl) in fp32 accum, error ~2^-16. Single QK^T pass into a
// 16x2048 smem score buffer (padded stride 2052), K streamed in 128-key
// double-buffered chunks. Then R1's proven warp-per-row Michelot sparsemax +
// sparse AV gather.

#define TQ      16
#define SEQ     2048
#define DIM     64
#define CH      128               // keys per chunk
#define NCHUNK  (SEQ / CH)        // 16
#define THREADS 512
#define SSTR    2052              // score row stride (floats), pad for banks

#define SM_SSC  0                                   // 16*2052*4 = 131328
#define SM_K    131328                              // 2buf*2term*128*36*4 = 73728
#define SM_QF   (131328 + 73728)                    // 16*64*4 = 4096
#define SMEM_TOTAL (SM_QF + 4096)                   // 209152

static __device__ __forceinline__ uint32_t pack2(__nv_bfloat16 x, __nv_bfloat16 y) {
    return (uint32_t)__bfloat16_as_ushort(x) | ((uint32_t)__bfloat16_as_ushort(y) << 16);
}

static __device__ __forceinline__ void mma16816(float* d, const uint32_t* a,
                                                uint32_t b0, uint32_t b1) {
    asm volatile(
        "mma.sync.aligned.m16n8k16.row.col.f32.bf16.bf16.f32 "
        "{%0,%1,%2,%3}, {%4,%5,%6,%7}, {%8,%9}, {%0,%1,%2,%3};"
        : "+f"(d[0]), "+f"(d[1]), "+f"(d[2]), "+f"(d[3])
        : "r"(a[0]), "r"(a[1]), "r"(a[2]), "r"(a[3]), "r"(b0), "r"(b1));
}

// K chunk loader: thread covers one key-quarter (16 dims). Splits fp32 into
// hi/lo bf16 and stores packed pairs into kb[buf][term][key][36 words].
static __device__ __forceinline__ void load_kchunk(uint32_t* kb, int buf,
                                                   const float* Kc,
                                                   int key, int qtr) {
    const float4* src = reinterpret_cast<const float4*>(Kc + (size_t)key * DIM + qtr * 16);
    float4 f0 = src[0], f1 = src[1], f2 = src[2], f3 = src[3];
    float e[16] = {f0.x,f0.y,f0.z,f0.w, f1.x,f1.y,f1.z,f1.w,
                   f2.x,f2.y,f2.z,f2.w, f3.x,f3.y,f3.z,f3.w};
    uint32_t wh = ((buf * 2 + 0) * CH + key) * 36 + qtr * 8;
    uint32_t wl = ((buf * 2 + 1) * CH + key) * 36 + qtr * 8;
    #pragma unroll
    for (int i = 0; i < 8; ++i) {
        float x0 = e[2*i], x1 = e[2*i+1];
        __nv_bfloat16 h0 = __float2bfloat16_rn(x0);
        __nv_bfloat16 l0 = __float2bfloat16_rn(x0 - __bfloat162float(h0));
        __nv_bfloat16 h1 = __float2bfloat16_rn(x1);
        __nv_bfloat16 l1 = __float2bfloat16_rn(x1 - __bfloat162float(h1));
        kb[wh + i] = pack2(h0, h1);
        kb[wl + i] = pack2(l0, l1);
    }
}

__global__ __launch_bounds__(THREADS, 1)
void entmax_attn_kernel(const float* __restrict__ Q, const float* __restrict__ K,
                        const float* __restrict__ V, float* __restrict__ O)
{
    extern __shared__ char smem[];
    float*    ssc = reinterpret_cast<float*>(smem + SM_SSC);
    uint32_t* kb  = reinterpret_cast<uint32_t*>(smem + SM_K);
    float*    qf  = reinterpret_cast<float*>(smem + SM_QF);

    const int bh = blockIdx.y;
    const int q0 = blockIdx.x * TQ;
    const float* Qb = Q + ((size_t)bh * SEQ + q0) * DIM;
    const float* Kb = K + (size_t)bh * SEQ * DIM;
    const float* Vb = V + (size_t)bh * SEQ * DIM;
    float*       Ob = O + ((size_t)bh * SEQ + q0) * DIM;

    const int tid  = threadIdx.x;
    const int wid  = tid >> 5;
    const int lane = tid & 31;
    const int g    = lane >> 2;     // mma group row
    const int t    = lane & 3;      // mma thread-in-quad

    // Stage Q (scaled 1/T) into smem.
    for (int i = tid; i < TQ * DIM; i += THREADS)
        qf[i] = Qb[i] * 0.125f;

    // Loader role: key 0..127, quarter 0..3.
    const int lkey = tid >> 2;
    const int lqtr = tid & 3;
    load_kchunk(kb, 0, Kb, lkey, lqtr);
    __syncthreads();

    // Build persistent A fragments (Qh, Ql) for the 4 k-steps.
    uint32_t Ah[4][4], Al[4][4];
    #pragma unroll
    for (int k0 = 0; k0 < 4; ++k0) {
        int c = 2 * t + 16 * k0;
        float e[8] = { qf[g*DIM + c],       qf[g*DIM + c + 1],
                       qf[(g+8)*DIM + c],   qf[(g+8)*DIM + c + 1],
                       qf[g*DIM + c + 8],   qf[g*DIM + c + 9],
                       qf[(g+8)*DIM + c+8], qf[(g+8)*DIM + c + 9] };
        __nv_bfloat16 h[8], l[8];
        #pragma unroll
        for (int i = 0; i < 8; ++i) {
            h[i] = __float2bfloat16_rn(e[i]);
            l[i] = __float2bfloat16_rn(e[i] - __bfloat162float(h[i]));
        }
        Ah[k0][0] = pack2(h[0], h[1]); Ah[k0][1] = pack2(h[2], h[3]);
        Ah[k0][2] = pack2(h[4], h[5]); Ah[k0][3] = pack2(h[6], h[7]);
        Al[k0][0] = pack2(l[0], l[1]); Al[k0][1] = pack2(l[2], l[3]);
        Al[k0][2] = pack2(l[4], l[5]); Al[k0][3] = pack2(l[6], l[7]);
    }

    // ---------------- Score GEMM: 16 double-buffered chunks ----------------
    const int keyloc = wid * 8 + g;                  // this lane's key in chunk
    for (int c = 0; c < NCHUNK; ++c) {
        const int buf = c & 1;

        // Issue next chunk's LDG early (overlaps with mma below).
        float4 nf0, nf1, nf2, nf3;
        if (c + 1 < NCHUNK) {
            const float4* src = reinterpret_cast<const float4*>(
                Kb + (size_t)((c + 1) * CH + lkey) * DIM + lqtr * 16);
            nf0 = src[0]; nf1 = src[1]; nf2 = src[2]; nf3 = src[3];
        }

        float D[4] = {0.f, 0.f, 0.f, 0.f};
        const uint32_t wbh = ((buf * 2 + 0) * CH + keyloc) * 36;
        const uint32_t wbl = ((buf * 2 + 1) * CH + keyloc) * 36;
        #pragma unroll
        for (int k0 = 0; k0 < 4; ++k0) {
            const int off = t + 8 * k0;
            uint32_t b0h = kb[wbh + off], b1h = kb[wbh + off + 4];
            uint32_t b0l = kb[wbl + off], b1l = kb[wbl + off + 4];
            mma16816(D, Ah[k0], b0h, b1h);
            mma16816(D, Al[k0], b0h, b1h);
            mma16816(D, Ah[k0], b0l, b1l);
        }

        // Scores: rows g, g+8; cols c*128 + wid*8 + 2t (+1).
        const int col = c * CH + wid * 8 + 2 * t;
        *reinterpret_cast<float2*>(ssc + (size_t)g * SSTR + col)       = make_float2(D[0], D[1]);
        *reinterpret_cast<float2*>(ssc + (size_t)(g + 8) * SSTR + col) = make_float2(D[2], D[3]);

        // Store next chunk into the other buffer.
        if (c + 1 < NCHUNK) {
            float e[16] = {nf0.x,nf0.y,nf0.z,nf0.w, nf1.x,nf1.y,nf1.z,nf1.w,
                           nf2.x,nf2.y,nf2.z,nf2.w, nf3.x,nf3.y,nf3.z,nf3.w};
            uint32_t wh = (((buf ^ 1) * 2 + 0) * CH + lkey) * 36 + lqtr * 8;
            uint32_t wl = (((buf ^ 1) * 2 + 1) * CH + lkey) * 36 + lqtr * 8;
            #pragma unroll
            for (int i = 0; i < 8; ++i) {
                float x0 = e[2*i], x1 = e[2*i+1];
                __nv_bfloat16 h0 = __float2bfloat16_rn(x0);
                __nv_bfloat16 l0 = __float2bfloat16_rn(x0 - __bfloat162float(h0));
                __nv_bfloat16 h1 = __float2bfloat16_rn(x1);
                __nv_bfloat16 l1 = __float2bfloat16_rn(x1 - __bfloat162float(h1));
                kb[wh + i] = pack2(h0, h1);
                kb[wl + i] = pack2(l0, l1);
            }
        }
        __syncthreads();
    }

    // ---------------- Sparsemax + sparse AV (R1-proven) ----------------
    const int r = wid;                               // warp per row
    float sreg[64];
    const float* srow = ssc + (size_t)r * SSTR;
    #pragma unroll
    for (int j = 0; j < 64; ++j) sreg[j] = srow[j * 32 + lane];

    float m = sreg[0];
    #pragma unroll
    for (int j = 1; j < 64; ++j) m = fmaxf(m, sreg[j]);
    #pragma unroll
    for (int off = 16; off; off >>= 1)
        m = fmaxf(m, __shfl_xor_sync(0xffffffffu, m, off));

    // Michelot fixed-point from tau0 = max-1 (monotone, bit-exact stop).
    float tau = m - 1.0f;
    for (int it = 0; it < 32; ++it) {
        float ssum = 0.0f, cntf = 0.0f;
        #pragma unroll
        for (int j = 0; j < 64; ++j) {
            if (sreg[j] > tau) { ssum += sreg[j]; cntf += 1.0f; }
        }
        #pragma unroll
        for (int off = 16; off; off >>= 1) {
            ssum += __shfl_xor_sync(0xffffffffu, ssum, off);
            cntf += __shfl_xor_sync(0xffffffffu, cntf, off);
        }
        float nt = (ssum - 1.0f) / cntf;             // cnt >= 1 (row max)
        if (nt == tau) break;                        // warp-uniform
        tau = nt;
    }

    float o0 = 0.0f, o1 = 0.0f;
    #pragma unroll
    for (int j = 0; j < 64; ++j) {
        float p = sreg[j] - tau;
        unsigned mset = __ballot_sync(0xffffffffu, p > 0.0f);
        while (mset) {
            int b = __ffs(mset) - 1;
            mset &= mset - 1;
            float pb = __shfl_sync(0xffffffffu, p, b);
            const float* vr = Vb + (size_t)(j * 32 + b) * DIM;
            o0 += pb * vr[lane];
            o1 += pb * vr[lane + 32];
        }
    }
    Ob[(size_t)r * DIM + lane]      = o0;
    Ob[(size_t)r * DIM + lane + 32] = o1;
}

extern "C" void kernel_launch(void* const* d_in, const int* in_sizes, int n_in,
                              void* d_out, int out_size)
{
    const float* q = (const float*)d_in[0];
    const float* k = (const float*)d_in[1];
    const float* v = (const float*)d_in[2];
    float*       o = (float*)d_out;

    const int BH = in_sizes[0] / (SEQ * DIM);   // 32

    cudaFuncSetAttribute(entmax_attn_kernel,
                         cudaFuncAttributeMaxDynamicSharedMemorySize, SMEM_TOTAL);

    dim3 grid(SEQ / TQ, BH);
    entmax_attn_kernel<<<grid, THREADS, SMEM_TOTAL>>>(q, k, v, o);
}

// round 12
// speedup vs baseline: 2.8630x; 1.5698x over previous
#include <cuda_runtime.h>
#include <cuda_bf16.h>
#include <cstdint>
#include <cstddef>

// EntmaxAttention, fp32 [B=2,H=16,S=2048,D=64], T=8.  mma.sync m16n8k16 bf16.
//
// R11 = R10 resubmission (broker timeout, never measured):
// K's 2-term bf16 Dekker split is precomputed ONCE by a pre-pass kernel
// into a __device__ fragment buffer in exact per-lane MMA B-fragment order
// (fragments are identical across all q-tile CTAs). Main kernel phase 1 is
// just prefetch-LDG.128 + 12 HMMA + score STS per chunk - no K smem, no
// conversion, no in-loop syncthreads. Phase 2/3: warp-per-row Michelot
// sparsemax + sparse AV gather (unchanged, proven).

#define TQ      16
#define SEQ     2048
#define DIM     64
#define CH      128
#define NCHUNK  (SEQ / CH)        // 16
#define THREADS 512
#define NBH     32                // B*H fixed for this problem
#define SSTR    2052              // score row stride (floats)

#define SM_SSC  0                                   // 16*2052*4 = 131328
#define SM_QF   131328                              // 16*64*4 = 4096
#define SMEM_TOTAL (SM_QF + 4096)                   // 135424

// B-fragment buffer: [bh][chunk][warp][lane] x 4 uint4 (16 words: 8 hi, 8 lo).
// 32*16*16*32 lanes * 64B = 16 MB.
__device__ __align__(16) uint4 g_kfrag[NBH * NCHUNK * 16 * 32 * 4];

static __device__ __forceinline__ uint32_t pack2(__nv_bfloat16 x, __nv_bfloat16 y) {
    return (uint32_t)__bfloat16_as_ushort(x) | ((uint32_t)__bfloat16_as_ushort(y) << 16);
}

static __device__ __forceinline__ void mma16816(float* d, const uint32_t* a,
                                                uint32_t b0, uint32_t b1) {
    asm volatile(
        "mma.sync.aligned.m16n8k16.row.col.f32.bf16.bf16.f32 "
        "{%0,%1,%2,%3}, {%4,%5,%6,%7}, {%8,%9}, {%0,%1,%2,%3};"
        : "+f"(d[0]), "+f"(d[1]), "+f"(d[2]), "+f"(d[3])
        : "r"(a[0]), "r"(a[1]), "r"(a[2]), "r"(a[3]), "r"(b0), "r"(b1));
}

static __device__ __forceinline__ void split2(float x, __nv_bfloat16& h, __nv_bfloat16& l) {
    h = __float2bfloat16_rn(x);
    l = __float2bfloat16_rn(x - __bfloat162float(h));
}

// Pre-pass: one thread per (bh, chunk, warp, lane) B-fragment row.
__global__ void kfrag_prep(const float* __restrict__ K) {
    int id = blockIdx.x * 256 + threadIdx.x;        // 0 .. 262143
    int lane  = id & 31;
    int warpid = (id >> 5) & 15;
    int chunk = (id >> 9) & 15;
    int bh    = id >> 13;
    int key = chunk * CH + warpid * 8 + (lane >> 2);
    int t = lane & 3;
    const float* kr = K + ((size_t)bh * SEQ + key) * DIM;

    uint32_t w[16];
    #pragma unroll
    for (int k0 = 0; k0 < 4; ++k0) {
        int d0 = 16 * k0 + 2 * t;
        float2 p0 = *reinterpret_cast<const float2*>(kr + d0);
        float2 p1 = *reinterpret_cast<const float2*>(kr + d0 + 8);
        __nv_bfloat16 h0,l0,h1,l1,h2,l2,h3,l3;
        split2(p0.x, h0, l0); split2(p0.y, h1, l1);
        split2(p1.x, h2, l2); split2(p1.y, h3, l3);
        w[2*k0]     = pack2(h0, h1);   // key-row word 8k0+t   (b0h)
        w[2*k0 + 1] = pack2(h2, h3);   // key-row word 8k0+t+4 (b1h)
        w[8 + 2*k0]     = pack2(l0, l1);
        w[8 + 2*k0 + 1] = pack2(l2, l3);
    }
    uint4* dst = g_kfrag + (size_t)id * 4;
    dst[0] = make_uint4(w[0],  w[1],  w[2],  w[3]);
    dst[1] = make_uint4(w[4],  w[5],  w[6],  w[7]);
    dst[2] = make_uint4(w[8],  w[9],  w[10], w[11]);
    dst[3] = make_uint4(w[12], w[13], w[14], w[15]);
}

__global__ __launch_bounds__(THREADS, 1)
void entmax_attn_kernel(const float* __restrict__ Q, const float* __restrict__ K,
                        const float* __restrict__ V, float* __restrict__ O)
{
    extern __shared__ char smem[];
    float* ssc = reinterpret_cast<float*>(smem + SM_SSC);
    float* qf  = reinterpret_cast<float*>(smem + SM_QF);

    const int bh = blockIdx.y;
    const int q0 = blockIdx.x * TQ;
    const float* Qb = Q + ((size_t)bh * SEQ + q0) * DIM;
    const float* Vb = V + (size_t)bh * SEQ * DIM;
    float*       Ob = O + ((size_t)bh * SEQ + q0) * DIM;

    const int tid  = threadIdx.x;
    const int wid  = tid >> 5;
    const int lane = tid & 31;
    const int g    = lane >> 2;
    const int t    = lane & 3;

    for (int i = tid; i < TQ * DIM; i += THREADS)
        qf[i] = Qb[i] * 0.125f;
    __syncthreads();

    // Persistent A fragments (Qh, Ql) for 4 k-steps.
    uint32_t Ah[4][4], Al[4][4];
    #pragma unroll
    for (int k0 = 0; k0 < 4; ++k0) {
        int c = 2 * t + 16 * k0;
        float e[8] = { qf[g*DIM + c],       qf[g*DIM + c + 1],
                       qf[(g+8)*DIM + c],   qf[(g+8)*DIM + c + 1],
                       qf[g*DIM + c + 8],   qf[g*DIM + c + 9],
                       qf[(g+8)*DIM + c+8], qf[(g+8)*DIM + c + 9] };
        __nv_bfloat16 h[8], l[8];
        #pragma unroll
        for (int i = 0; i < 8; ++i) split2(e[i], h[i], l[i]);
        Ah[k0][0] = pack2(h[0], h[1]); Ah[k0][1] = pack2(h[2], h[3]);
        Ah[k0][2] = pack2(h[4], h[5]); Ah[k0][3] = pack2(h[6], h[7]);
        Al[k0][0] = pack2(l[0], l[1]); Al[k0][1] = pack2(l[2], l[3]);
        Al[k0][2] = pack2(l[4], l[5]); Al[k0][3] = pack2(l[6], l[7]);
    }

    // ---------------- Phase 1: QK^T, fragments streamed from L2 ----------------
    const uint4* fb = g_kfrag + ((size_t)((bh * NCHUNK) * 16 + wid) * 32 + lane) * 4;
    const size_t cstride = (size_t)16 * 32 * 4;     // uint4 per chunk

    uint4 c0 = fb[0], c1 = fb[1], c2 = fb[2], c3 = fb[3];
    for (int c = 0; c < NCHUNK; ++c) {
        uint4 n0, n1, n2, n3;
        if (c + 1 < NCHUNK) {
            const uint4* nf = fb + (size_t)(c + 1) * cstride;
            n0 = nf[0]; n1 = nf[1]; n2 = nf[2]; n3 = nf[3];
        }

        float D[4] = {0.f, 0.f, 0.f, 0.f};
        // k0=0
        mma16816(D, Ah[0], c0.x, c0.y);
        mma16816(D, Al[0], c0.x, c0.y);
        mma16816(D, Ah[0], c2.x, c2.y);
        // k0=1
        mma16816(D, Ah[1], c0.z, c0.w);
        mma16816(D, Al[1], c0.z, c0.w);
        mma16816(D, Ah[1], c2.z, c2.w);
        // k0=2
        mma16816(D, Ah[2], c1.x, c1.y);
        mma16816(D, Al[2], c1.x, c1.y);
        mma16816(D, Ah[2], c3.x, c3.y);
        // k0=3
        mma16816(D, Ah[3], c1.z, c1.w);
        mma16816(D, Al[3], c1.z, c1.w);
        mma16816(D, Ah[3], c3.z, c3.w);

        const int col = c * CH + wid * 8 + 2 * t;
        *reinterpret_cast<float2*>(ssc + (size_t)g * SSTR + col)       = make_float2(D[0], D[1]);
        *reinterpret_cast<float2*>(ssc + (size_t)(g + 8) * SSTR + col) = make_float2(D[2], D[3]);

        c0 = n0; c1 = n1; c2 = n2; c3 = n3;
    }
    __syncthreads();

    // ---------------- Phase 2+3: sparsemax + sparse AV ----------------
    const int r = wid;
    float sreg[64];
    const float* srow = ssc + (size_t)r * SSTR;
    #pragma unroll
    for (int j = 0; j < 64; ++j) sreg[j] = srow[j * 32 + lane];

    float m = sreg[0];
    #pragma unroll
    for (int j = 1; j < 64; ++j) m = fmaxf(m, sreg[j]);
    #pragma unroll
    for (int off = 16; off; off >>= 1)
        m = fmaxf(m, __shfl_xor_sync(0xffffffffu, m, off));

    float tau = m - 1.0f;
    for (int it = 0; it < 32; ++it) {
        float ssum = 0.0f, cntf = 0.0f;
        #pragma unroll
        for (int j = 0; j < 64; ++j) {
            if (sreg[j] > tau) { ssum += sreg[j]; cntf += 1.0f; }
        }
        #pragma unroll
        for (int off = 16; off; off >>= 1) {
            ssum += __shfl_xor_sync(0xffffffffu, ssum, off);
            cntf += __shfl_xor_sync(0xffffffffu, cntf, off);
        }
        float nt = (ssum - 1.0f) / cntf;
        if (nt == tau) break;
        tau = nt;
    }

    float o0 = 0.0f, o1 = 0.0f;
    #pragma unroll
    for (int j = 0; j < 64; ++j) {
        float p = sreg[j] - tau;
        unsigned mset = __ballot_sync(0xffffffffu, p > 0.0f);
        while (mset) {
            int b = __ffs(mset) - 1;
            mset &= mset - 1;
            float pb = __shfl_sync(0xffffffffu, p, b);
            const float* vr = Vb + (size_t)(j * 32 + b) * DIM;
            o0 += pb * vr[lane];
            o1 += pb * vr[lane + 32];
        }
    }
    Ob[(size_t)r * DIM + lane]      = o0;
    Ob[(size_t)r * DIM + lane + 32] = o1;
}

extern "C" void kernel_launch(void* const* d_in, const int* in_sizes, int n_in,
                              void* d_out, int out_size)
{
    const float* q = (const float*)d_in[0];
    const float* k = (const float*)d_in[1];
    const float* v = (const float*)d_in[2];
    float*       o = (float*)d_out;

    const int BH = in_sizes[0] / (SEQ * DIM);   // 32

    kfrag_prep<<<(NBH * NCHUNK * 16 * 32) / 256, 256>>>(k);

    cudaFuncSetAttribute(entmax_attn_kernel,
                         cudaFuncAttributeMaxDynamicSharedMemorySize, SMEM_TOTAL);
    dim3 grid(SEQ / TQ, BH);
    entmax_attn_kernel<<<grid, THREADS, SMEM_TOTAL>>>(q, k, v, o);
}